// round 8
// baseline (speedup 1.0000x reference)
#include <cuda_runtime.h>
#include <math.h>

#define JJN  20
#define NH   16
#define NSEQ 8192
#define NB   8
#define HD4  16          // float4 per 64-float row
#define GROUPS 32        // 256 threads / 8 lanes
#define POS_PER_CTA 128  // GROUPS * 4
#define EPOS 24
#define EGRP 100
#define NDROW 18         // dense rows: t = -15..2
#define NDSLOT 48        // dense pairs (offsets 1..15 => j = 0..11)
#define FARJ0 12         // far offsets j = 12..19: {16,23,32,64,128,256,512,1024}

// Dense consumer tables (lane-divergent access, hoisted ONCE per warp).
__constant__ int cD_T[NDSLOT] = {
    -15,-14,-13,-13,-12,-12,-11,-11,-10,-10,-9,-9,-8,-8,-8,-7,-7,-7,
    -6,-6,-6,-6,-5,-5,-5,-5,-4,-4,-4,-4,-3,-3,-3,-3,-2,-2,-2,-2,
    -1,-1,-1,-1,0,0,0,1,1,2 };
__constant__ int cD_P[NDSLOT] = {
    0,1,0,2,1,3,0,2,1,3,0,2,0,1,3,0,1,2,
    0,1,2,3,0,1,2,3,0,1,2,3,0,1,2,3,0,1,2,3,
    0,1,2,3,1,2,3,2,3,3 };
__constant__ int cD_J[NDSLOT] = {
    11,11,10,11,10,11,9,10,9,10,8,9,7,8,9,6,7,8,
    5,6,7,8,4,5,6,7,3,4,5,6,2,3,4,5,1,2,3,4,
    0,1,2,3,0,1,2,0,1,0 };

// ---- packed f32x2 helpers ----
struct f2 { unsigned long long u; };
__device__ __forceinline__ f2 fpack(float x, float y) {
    f2 r; asm("mov.b64 %0, {%1,%2};" : "=l"(r.u) : "f"(x), "f"(y)); return r;
}
__device__ __forceinline__ f2 ffma2(f2 a, f2 b, f2 c) {
    f2 r; asm("fma.rn.f32x2 %0, %1, %2, %3;" : "=l"(r.u) : "l"(a.u), "l"(b.u), "l"(c.u)); return r;
}
__device__ __forceinline__ f2 fmul2(f2 a, f2 b) {
    f2 r; asm("mul.rn.f32x2 %0, %1, %2;" : "=l"(r.u) : "l"(a.u), "l"(b.u)); return r;
}
__device__ __forceinline__ void funpack(f2 a, float& x, float& y) {
    asm("mov.b64 {%0,%1}, %2;" : "=f"(x), "=f"(y) : "l"(a.u));
}
__device__ __forceinline__ float ex2f(float x) {
    float r; asm("ex2.approx.f32 %0, %1;" : "=f"(r) : "f"(x)); return r;
}

// 8-lane x 8-partial butterfly reduce-scatter: lane l gets full sum of slot l.
__device__ __forceinline__ float rscatter8(float part[8], int lane8) {
    {
        const bool hi = (lane8 & 4) != 0;
        #pragma unroll
        for (int i = 0; i < 4; i++) {
            float keep = hi ? part[i + 4] : part[i];
            float send = hi ? part[i]     : part[i + 4];
            part[i] = keep + __shfl_xor_sync(0xffffffffu, send, 4);
        }
    }
    {
        const bool hi = (lane8 & 2) != 0;
        #pragma unroll
        for (int i = 0; i < 2; i++) {
            float keep = hi ? part[i + 2] : part[i];
            float send = hi ? part[i]     : part[i + 2];
            part[i] = keep + __shfl_xor_sync(0xffffffffu, send, 2);
        }
    }
    {
        const bool hi = (lane8 & 1) != 0;
        float keep = hi ? part[1] : part[0];
        float send = hi ? part[0] : part[1];
        return keep + __shfl_xor_sync(0xffffffffu, send, 1);
    }
}

__global__ __launch_bounds__(256, 2)
void dsqg_attn_kernel(const float* __restrict__ q,
                      const float* __restrict__ k,
                      const float* __restrict__ v,
                      const float* __restrict__ pos_bias,     // [J, H]
                      const float* __restrict__ scale_embed,  // [J, HD]
                      float* __restrict__ out)
{
    const int OFF[JJN] = {1,2,3,4,5,6,7,8,9,11,13,15,16,23,32,64,128,256,512,1024};
    // Dense schedule (compile-time-indexed only)
    const int DROWT[NDROW] = {-15,-14,-13,-12,-11,-10,-9,-8,-7,-6,-5,-4,-3,-2,-1,0,1,2};
    const int DROW[NDSLOT] = {
        0,1,2,2,3,3,4,4,5,5,6,6,7,7,7,8,8,8,
        9,9,9,9,10,10,10,10,11,11,11,11,12,12,12,12,13,13,13,13,
        14,14,14,14,15,15,15,16,16,17 };
    const int DP[NDSLOT] = {
        0,1,0,2,1,3,0,2,1,3,0,2,0,1,3,0,1,2,
        0,1,2,3,0,1,2,3,0,1,2,3,0,1,2,3,0,1,2,3,
        0,1,2,3,1,2,3,2,3,3 };
    const int DJ[NDSLOT] = {
        11,11,10,11,10,11,9,10,9,10,8,9,7,8,9,6,7,8,
        5,6,7,8,4,5,6,7,3,4,5,6,2,3,4,5,1,2,3,4,
        0,1,2,3,0,1,2,0,1,0 };

    __shared__ float4 s_se[JJN][HD4];     // 5 KB
    __shared__ float  s_pb[JJN];
    __shared__ float  s_e[GROUPS * EGRP]; // 12.8 KB

    const int blocks_per_seq = NSEQ / POS_PER_CTA;          // 64
    const int bh   = blockIdx.x / blocks_per_seq;
    const int seq0 = (blockIdx.x % blocks_per_seq) * POS_PER_CTA;
    const int h    = bh % NH;

    const float LOG2E = 1.4426950408889634f;
    for (int i = threadIdx.x; i < JJN * HD4; i += 256)
        ((float4*)s_se)[i] = ((const float4*)scale_embed)[i];
    if (threadIdx.x < JJN)
        s_pb[threadIdx.x] = pos_bias[threadIdx.x * NH + h] * LOG2E;
    __syncthreads();

    const int gid   = threadIdx.x >> 3;
    const int lane8 = threadIdx.x & 7;
    const int n0    = seq0 + gid * 4;
    const int egbase = gid * EGRP;

    const size_t bh_row0 = (size_t)bh * NSEQ * HD4;
    const float4* __restrict__ kb4 = (const float4*)k + bh_row0;
    const float4* __restrict__ vb4 = (const float4*)v + bh_row0;
    const float4* __restrict__ qb4 = (const float4*)q + bh_row0;

    // q pre-scaled by (1/sqrt(64)) * log2(e) so e = ex2(score)
    const float qs = 0.125f * LOG2E;
    f2 qv[4][4];
    #pragma unroll
    for (int p = 0; p < 4; p++) {
        const float4* qr = qb4 + (size_t)(n0 + p) * HD4;
        float4 a = qr[lane8], b = qr[lane8 + 8];
        qv[p][0] = fpack(a.x * qs, a.y * qs);
        qv[p][1] = fpack(a.z * qs, a.w * qs);
        qv[p][2] = fpack(b.x * qs, b.y * qs);
        qv[p][3] = fpack(b.z * qs, b.w * qs);
    }

    float part[8];

    // ========== PHASE 0: qse[p][j] = q.se_j*sc*log2e + pb_j*log2e -> s_e ==========
    {
        f2 s0, s1, s2, s3;
        #pragma unroll
        for (int i = 0; i < 80; i++) {
            const int j = i >> 2;
            if ((i & 3) == 0) {
                float4 sa = s_se[j][lane8], sb = s_se[j][lane8 + 8];
                s0 = fpack(sa.x, sa.y); s1 = fpack(sa.z, sa.w);
                s2 = fpack(sb.x, sb.y); s3 = fpack(sb.z, sb.w);
            }
            const int p = i & 3;
            f2 a = fmul2(qv[p][0], s0);
            a = ffma2(qv[p][1], s1, a);
            a = ffma2(qv[p][2], s2, a);
            a = ffma2(qv[p][3], s3, a);
            float x, y; funpack(a, x, y);
            part[i & 7] = x + y;
            if ((i & 7) == 7) {
                float red = rscatter8(part, lane8);
                const int pp = lane8 & 3;
                const int jj = 2 * (i >> 3) + (lane8 >> 2);
                s_e[egbase + pp * EPOS + jj] = red + s_pb[jj];
            }
        }
    }
    __syncwarp();

    const int ppE = (lane8 & 3) * EPOS;   // hoisted consumer addr component
    const int l4  = lane8 >> 2;

    // ========== PHASE 1a: far offsets (j=12..19), 4 batches of 8 rows ==========
    {
        f2 kbuf[8][4];
        // batch 0 loads
        #pragma unroll
        for (int i = 0; i < 8; i++) {
            const int d = OFF[FARJ0 + (i >> 2)];
            int r = n0 + (i & 3) - d;
            int rc = (r < 0) ? 0 : r;
            const float4* kr = kb4 + (size_t)rc * HD4;
            float4 a = kr[lane8], b = kr[lane8 + 8];
            kbuf[i][0] = fpack(a.x, a.y); kbuf[i][1] = fpack(a.z, a.w);
            kbuf[i][2] = fpack(b.x, b.y); kbuf[i][3] = fpack(b.z, b.w);
        }
        #pragma unroll
        for (int b = 0; b < 4; b++) {
            #pragma unroll
            for (int i = 0; i < 8; i++) {
                const int p = i & 3;
                f2 a = fmul2(qv[p][0], kbuf[i][0]);
                a = ffma2(qv[p][1], kbuf[i][1], a);
                a = ffma2(qv[p][2], kbuf[i][2], a);
                a = ffma2(qv[p][3], kbuf[i][3], a);
                float x, y; funpack(a, x, y);
                part[i] = x + y;
            }
            if (b < 3) {   // prefetch next batch before the reduce
                #pragma unroll
                for (int i = 0; i < 8; i++) {
                    const int d = OFF[FARJ0 + 2 * (b + 1) + (i >> 2)];
                    int r = n0 + (i & 3) - d;
                    int rc = (r < 0) ? 0 : r;
                    const float4* kr = kb4 + (size_t)rc * HD4;
                    float4 a = kr[lane8], bb = kr[lane8 + 8];
                    kbuf[i][0] = fpack(a.x, a.y); kbuf[i][1] = fpack(a.z, a.w);
                    kbuf[i][2] = fpack(bb.x, bb.y); kbuf[i][3] = fpack(bb.z, bb.w);
                }
            }
            float red = rscatter8(part, lane8);
            const int dA = OFF[FARJ0 + 2 * b], dB = OFF[FARJ0 + 2 * b + 1];
            const int dd = (lane8 >= 4) ? dB : dA;
            const float validf = (n0 + (lane8 & 3) - dd >= 0) ? 1.0f : 0.0f;
            const int addr = egbase + ppE + (FARJ0 + 2 * b + l4);
            float e = ex2f(red + s_e[addr]) * validf;
            s_e[addr] = e;
        }
    }

    // ========== PHASE 1b: dense offsets (j=0..11), 18 rows, ring-4 ==========
    {
        int   daddr[6];
        float dval[6];
        #pragma unroll
        for (int b = 0; b < 6; b++) {     // one-time divergent LDC, out of hot loop
            const int s0i = 8 * b + lane8;
            daddr[b] = egbase + cD_P[s0i] * EPOS + cD_J[s0i];
            dval[b]  = (n0 + cD_T[s0i] >= 0) ? 1.0f : 0.0f;
        }

        f2 kr4[4][4];
        #pragma unroll
        for (int r = 0; r < 4; r++) {
            int rr = n0 + DROWT[r];
            int rc = (rr < 0) ? 0 : rr;
            const float4* kr = kb4 + (size_t)rc * HD4;
            float4 a = kr[lane8], b = kr[lane8 + 8];
            kr4[r][0] = fpack(a.x, a.y); kr4[r][1] = fpack(a.z, a.w);
            kr4[r][2] = fpack(b.x, b.y); kr4[r][3] = fpack(b.z, b.w);
        }
        #pragma unroll
        for (int i = 0; i < NDSLOT; i++) {
            const int r = DROW[i], bi = r & 3, p = DP[i];
            f2 a = fmul2(qv[p][0], kr4[bi][0]);
            a = ffma2(qv[p][1], kr4[bi][1], a);
            a = ffma2(qv[p][2], kr4[bi][2], a);
            a = ffma2(qv[p][3], kr4[bi][3], a);
            float x, y; funpack(a, x, y);
            part[i & 7] = x + y;

            const bool last = (i == NDSLOT - 1) || (DROW[i + (i < NDSLOT - 1 ? 1 : 0)] != r) || (i == NDSLOT - 1);
            if (((i == NDSLOT - 1) || (DROW[i + 1] != r)) && (r + 4) < NDROW) {
                int rr = n0 + DROWT[r + 4];
                int rc = (rr < 0) ? 0 : rr;
                const float4* kr = kb4 + (size_t)rc * HD4;
                float4 fa = kr[lane8], fb = kr[lane8 + 8];
                kr4[bi][0] = fpack(fa.x, fa.y); kr4[bi][1] = fpack(fa.z, fa.w);
                kr4[bi][2] = fpack(fb.x, fb.y); kr4[bi][3] = fpack(fb.z, fb.w);
            }
            (void)last;
            if ((i & 7) == 7) {
                const int b = i >> 3;
                float red = rscatter8(part, lane8);
                float e = ex2f(red + s_e[daddr[b]]) * dval[b];
                s_e[daddr[b]] = e;
            }
        }
    }
    __syncwarp();

    // ========== denominators ==========
    if (lane8 < 4) {
        const float4* ep = (const float4*)&s_e[egbase + lane8 * EPOS];
        float4 a = ep[0], b = ep[1], c = ep[2], d = ep[3], e4 = ep[4];
        float s = a.x + a.y + a.z + a.w + b.x + b.y + b.z + b.w
                + c.x + c.y + c.z + c.w + d.x + d.y + d.z + d.w
                + e4.x + e4.y + e4.z + e4.w;
        s_e[egbase + lane8 * EPOS + 20] = 1.0f / fmaxf(s, 1e-30f);
    }
    __syncwarp();

    // ========== PHASE 2: out = (sum e*v) * inv ==========
    {
        f2 oacc[4][4];
        #pragma unroll
        for (int p = 0; p < 4; p++)
            #pragma unroll
            for (int c = 0; c < 4; c++) oacc[p][c] = fpack(0.f, 0.f);

        // -- far batches --
        {
            f2 vbuf[8][4];
            #pragma unroll
            for (int i = 0; i < 8; i++) {
                const int d = OFF[FARJ0 + (i >> 2)];
                int r = n0 + (i & 3) - d;
                int rc = (r < 0) ? 0 : r;
                const float4* vr = vb4 + (size_t)rc * HD4;
                float4 a = vr[lane8], b = vr[lane8 + 8];
                vbuf[i][0] = fpack(a.x, a.y); vbuf[i][1] = fpack(a.z, a.w);
                vbuf[i][2] = fpack(b.x, b.y); vbuf[i][3] = fpack(b.z, b.w);
            }
            #pragma unroll
            for (int b = 0; b < 4; b++) {
                float ev[8];
                #pragma unroll
                for (int i = 0; i < 8; i++)
                    ev[i] = s_e[egbase + (i & 3) * EPOS + (FARJ0 + 2 * b + (i >> 2))];
                #pragma unroll
                for (int i = 0; i < 8; i++) {
                    const int p = i & 3;
                    f2 e2 = fpack(ev[i], ev[i]);
                    oacc[p][0] = ffma2(e2, vbuf[i][0], oacc[p][0]);
                    oacc[p][1] = ffma2(e2, vbuf[i][1], oacc[p][1]);
                    oacc[p][2] = ffma2(e2, vbuf[i][2], oacc[p][2]);
                    oacc[p][3] = ffma2(e2, vbuf[i][3], oacc[p][3]);
                }
                if (b < 3) {
                    #pragma unroll
                    for (int i = 0; i < 8; i++) {
                        const int d = OFF[FARJ0 + 2 * (b + 1) + (i >> 2)];
                        int r = n0 + (i & 3) - d;
                        int rc = (r < 0) ? 0 : r;
                        const float4* vr = vb4 + (size_t)rc * HD4;
                        float4 a = vr[lane8], bb = vr[lane8 + 8];
                        vbuf[i][0] = fpack(a.x, a.y); vbuf[i][1] = fpack(a.z, a.w);
                        vbuf[i][2] = fpack(bb.x, bb.y); vbuf[i][3] = fpack(bb.z, bb.w);
                    }
                }
            }
        }

        // -- dense ring --
        {
            f2 vr4[4][4];
            #pragma unroll
            for (int r = 0; r < 4; r++) {
                int rr = n0 + DROWT[r];
                int rc = (rr < 0) ? 0 : rr;
                const float4* vr = vb4 + (size_t)rc * HD4;
                float4 a = vr[lane8], b = vr[lane8 + 8];
                vr4[r][0] = fpack(a.x, a.y); vr4[r][1] = fpack(a.z, a.w);
                vr4[r][2] = fpack(b.x, b.y); vr4[r][3] = fpack(b.z, b.w);
            }
            #pragma unroll
            for (int i = 0; i < NDSLOT; i++) {
                const int r = DROW[i], bi = r & 3, p = DP[i];
                const float e = s_e[egbase + DP[i] * EPOS + DJ[i]];
                f2 e2 = fpack(e, e);
                oacc[p][0] = ffma2(e2, vr4[bi][0], oacc[p][0]);
                oacc[p][1] = ffma2(e2, vr4[bi][1], oacc[p][1]);
                oacc[p][2] = ffma2(e2, vr4[bi][2], oacc[p][2]);
                oacc[p][3] = ffma2(e2, vr4[bi][3], oacc[p][3]);
                if (((i == NDSLOT - 1) || (DROW[i + 1] != r)) && (r + 4) < NDROW) {
                    int rr = n0 + DROWT[r + 4];
                    int rc = (rr < 0) ? 0 : rr;
                    const float4* vr = vb4 + (size_t)rc * HD4;
                    float4 fa = vr[lane8], fb = vr[lane8 + 8];
                    vr4[bi][0] = fpack(fa.x, fa.y); vr4[bi][1] = fpack(fa.z, fa.w);
                    vr4[bi][2] = fpack(fb.x, fb.y); vr4[bi][3] = fpack(fb.z, fb.w);
                }
            }
        }

        #pragma unroll
        for (int p = 0; p < 4; p++) {
            const float inv = s_e[egbase + p * EPOS + 20];
            f2 iv = fpack(inv, inv);
            f2 r0 = fmul2(oacc[p][0], iv);
            f2 r1 = fmul2(oacc[p][1], iv);
            f2 r2 = fmul2(oacc[p][2], iv);
            f2 r3 = fmul2(oacc[p][3], iv);
            float4 oA, oB;
            funpack(r0, oA.x, oA.y); funpack(r1, oA.z, oA.w);
            funpack(r2, oB.x, oB.y); funpack(r3, oB.z, oB.w);
            float4* o4 = (float4*)out + bh_row0 + (size_t)(n0 + p) * HD4;
            o4[lane8]     = oA;
            o4[lane8 + 8] = oB;
        }
    }
}

extern "C" void kernel_launch(void* const* d_in, const int* in_sizes, int n_in,
                              void* d_out, int out_size)
{
    const float* q  = (const float*)d_in[0];
    const float* k  = (const float*)d_in[1];
    const float* v  = (const float*)d_in[2];
    const float* pb = (const float*)d_in[3];
    const float* se = (const float*)d_in[4];
    float* out = (float*)d_out;

    const int blocks = NB * NH * (NSEQ / POS_PER_CTA);   // 8192
    dsqg_attn_kernel<<<blocks, 256>>>(q, k, v, pb, se, out);
}

// round 9
// speedup vs baseline: 1.0688x; 1.0688x over previous
#include <cuda_runtime.h>
#include <math.h>

#define JJN  20
#define NH   16
#define NSEQ 8192
#define NB   8
#define HD4  16          // float4 per 64-float row
#define GROUPS 32        // 256 threads / 8 lanes
#define POS_PER_CTA 128  // GROUPS * 4
#define EPOS 24          // float stride per position inside a group's e-block
#define EGRP 100         // float stride per group
#define NROW 47
#define NSLOT 80
#define RING 4

// Runtime-lane-indexed copies (consumer side of the reduce-scatter).
// Far-to-near row order.
__constant__ int c_T[NSLOT] = {
    -1024,-1023,-1022,-1021,-512,-511,-510,-509,-256,-255,-254,-253,
    -128,-127,-126,-125,-64,-63,-62,-61,-32,-31,-30,-29,-23,-22,-21,-20,-16,
    -15,-15,-14,-14,-13,-13,-13,-12,-12,-11,-11,-10,-10,-9,-9,-8,-8,-8,-7,-7,-7,
    -6,-6,-6,-6,-5,-5,-5,-5,-4,-4,-4,-4,-3,-3,-3,-3,-2,-2,-2,-2,-1,-1,-1,-1,
    0,0,0,1,1,2 };
__constant__ int c_P[NSLOT] = {
    0,1,2,3, 0,1,2,3, 0,1,2,3, 0,1,2,3, 0,1,2,3, 0,1,2,3, 0,1,2,3, 0,
    0,1, 1,2, 0,2,3, 1,3, 0,2, 1,3, 0,2, 0,1,3, 0,1,2,
    0,1,2,3, 0,1,2,3, 0,1,2,3, 0,1,2,3, 0,1,2,3, 0,1,2,3,
    1,2,3, 2,3, 3 };
__constant__ int c_J[NSLOT] = {
    19,19,19,19, 18,18,18,18, 17,17,17,17, 16,16,16,16, 15,15,15,15,
    14,14,14,14, 13,13,13,13, 12,
    11,12, 11,12, 10,11,12, 10,11, 9,10, 9,10, 8,9, 7,8,9, 6,7,8,
    5,6,7,8, 4,5,6,7, 3,4,5,6, 2,3,4,5, 1,2,3,4, 0,1,2,3,
    0,1,2, 0,1, 0 };

// ---- packed f32x2 helpers ----
struct f2 { unsigned long long u; };
__device__ __forceinline__ f2 fpack(float x, float y) {
    f2 r; asm("mov.b64 %0, {%1,%2};" : "=l"(r.u) : "f"(x), "f"(y)); return r;
}
__device__ __forceinline__ f2 ffma2(f2 a, f2 b, f2 c) {
    f2 r; asm("fma.rn.f32x2 %0, %1, %2, %3;" : "=l"(r.u) : "l"(a.u), "l"(b.u), "l"(c.u)); return r;
}
__device__ __forceinline__ f2 fmul2(f2 a, f2 b) {
    f2 r; asm("mul.rn.f32x2 %0, %1, %2;" : "=l"(r.u) : "l"(a.u), "l"(b.u)); return r;
}
__device__ __forceinline__ void funpack(f2 a, float& x, float& y) {
    asm("mov.b64 {%0,%1}, %2;" : "=f"(x), "=f"(y) : "l"(a.u));
}
__device__ __forceinline__ float ex2f(float x) {
    float r; asm("ex2.approx.f32 %0, %1;" : "=f"(r) : "f"(x)); return r;
}
__device__ __forceinline__ void prefetchL1(const void* p) {
    asm volatile("prefetch.global.L1 [%0];" :: "l"(p));
}

// 8-lane x 8-partial butterfly reduce-scatter: lane l gets full sum of slot l.
__device__ __forceinline__ float rscatter8(float part[8], int lane8) {
    {
        const bool hi = (lane8 & 4) != 0;
        #pragma unroll
        for (int i = 0; i < 4; i++) {
            float keep = hi ? part[i + 4] : part[i];
            float send = hi ? part[i]     : part[i + 4];
            part[i] = keep + __shfl_xor_sync(0xffffffffu, send, 4);
        }
    }
    {
        const bool hi = (lane8 & 2) != 0;
        #pragma unroll
        for (int i = 0; i < 2; i++) {
            float keep = hi ? part[i + 2] : part[i];
            float send = hi ? part[i]     : part[i + 2];
            part[i] = keep + __shfl_xor_sync(0xffffffffu, send, 2);
        }
    }
    {
        const bool hi = (lane8 & 1) != 0;
        float keep = hi ? part[1] : part[0];
        float send = hi ? part[0] : part[1];
        return keep + __shfl_xor_sync(0xffffffffu, send, 1);
    }
}

__global__ __launch_bounds__(256, 3)
void dsqg_attn_kernel(const float* __restrict__ q,
                      const float* __restrict__ k,
                      const float* __restrict__ v,
                      const float* __restrict__ pos_bias,     // [J, H]
                      const float* __restrict__ scale_embed,  // [J, HD]
                      float* __restrict__ out)
{
    // Compile-time schedule (flat, fully unrolled everywhere it is indexed).
    const int ROW_T[NROW] = {
        -1024,-1023,-1022,-1021, -512,-511,-510,-509, -256,-255,-254,-253,
        -128,-127,-126,-125, -64,-63,-62,-61, -32,-31,-30,-29, -23,-22,-21,-20,
        -16,-15,-14,-13,-12,-11,-10,-9,-8,-7,-6,-5,-4,-3,-2,-1,0,1,2 };
    const int SLOT_ROW[NSLOT] = {
        0,1,2,3,4,5,6,7,8,9,10,11,12,13,14,15,16,17,18,19,20,21,22,23,24,25,26,27,28,
        29,29, 30,30, 31,31,31, 32,32, 33,33, 34,34, 35,35, 36,36,36, 37,37,37,
        38,38,38,38, 39,39,39,39, 40,40,40,40, 41,41,41,41, 42,42,42,42, 43,43,43,43,
        44,44,44, 45,45, 46 };
    const int SLOT_P[NSLOT] = {
        0,1,2,3, 0,1,2,3, 0,1,2,3, 0,1,2,3, 0,1,2,3, 0,1,2,3, 0,1,2,3, 0,
        0,1, 1,2, 0,2,3, 1,3, 0,2, 1,3, 0,2, 0,1,3, 0,1,2,
        0,1,2,3, 0,1,2,3, 0,1,2,3, 0,1,2,3, 0,1,2,3, 0,1,2,3,
        1,2,3, 2,3, 3 };
    const int SLOT_J[NSLOT] = {
        19,19,19,19, 18,18,18,18, 17,17,17,17, 16,16,16,16, 15,15,15,15,
        14,14,14,14, 13,13,13,13, 12,
        11,12, 11,12, 10,11,12, 10,11, 9,10, 9,10, 8,9, 7,8,9, 6,7,8,
        5,6,7,8, 4,5,6,7, 3,4,5,6, 2,3,4,5, 1,2,3,4, 0,1,2,3,
        0,1,2, 0,1, 0 };

    __shared__ float4 s_se[JJN][HD4];     // 5 KB
    __shared__ float  s_pb[JJN];
    __shared__ float  s_e[GROUPS * EGRP]; // 12.8 KB

    const int blocks_per_seq = NSEQ / POS_PER_CTA;          // 64
    const int bh   = blockIdx.x / blocks_per_seq;
    const int seq0 = (blockIdx.x % blocks_per_seq) * POS_PER_CTA;
    const int h    = bh % NH;

    const float LOG2E = 1.4426950408889634f;
    for (int i = threadIdx.x; i < JJN * HD4; i += 256)
        ((float4*)s_se)[i] = ((const float4*)scale_embed)[i];
    if (threadIdx.x < JJN)
        s_pb[threadIdx.x] = pos_bias[threadIdx.x * NH + h] * LOG2E;
    __syncthreads();

    const int gid   = threadIdx.x >> 3;    // 0..31
    const int lane8 = threadIdx.x & 7;     // 0..7
    const int n0    = seq0 + gid * 4;
    const int egbase = gid * EGRP;

    const size_t bh_row0 = (size_t)bh * NSEQ * HD4;
    const float4* __restrict__ kb4 = (const float4*)k + bh_row0;
    const float4* __restrict__ vb4 = (const float4*)v + bh_row0;
    const float4* __restrict__ qb4 = (const float4*)q + bh_row0;

    // ---- L1 prefetch of the 16 truly-far rows (t <= -125), k and v.
    // Lanes 0-3 cover line 0, lanes 4-7 line 1 of each 256B row.
    {
        const int loff = ((lane8 & 4) ? 128 : 0) + (lane8 & 3) * 32;
        #pragma unroll
        for (int r = 0; r < 16; r++) {
            int rr = n0 + ROW_T[r];
            int rc = (rr < 0) ? 0 : rr;
            prefetchL1((const char*)(kb4 + (size_t)rc * HD4) + loff);
            prefetchL1((const char*)(vb4 + (size_t)rc * HD4) + loff);
        }
    }

    // q pre-scaled by (1/sqrt(64))*log2(e) so e = ex2(dot + qse_term)
    const float qs = 0.125f * LOG2E;
    f2 qv[4][4];
    #pragma unroll
    for (int p = 0; p < 4; p++) {
        const float4* qr = qb4 + (size_t)(n0 + p) * HD4;
        float4 a = qr[lane8], b = qr[lane8 + 8];
        qv[p][0] = fpack(a.x * qs, a.y * qs);
        qv[p][1] = fpack(a.z * qs, a.w * qs);
        qv[p][2] = fpack(b.x * qs, b.y * qs);
        qv[p][3] = fpack(b.z * qs, b.w * qs);
    }

    float part[8];

    // ========== PHASE 0: qse[p][j] = q.se_j (scaled) + pb_j -> s_e ==========
    {
        f2 s0, s1, s2, s3;
        #pragma unroll
        for (int i = 0; i < 80; i++) {
            const int j = i >> 2;
            if ((i & 3) == 0) {
                float4 sa = s_se[j][lane8], sb = s_se[j][lane8 + 8];
                s0 = fpack(sa.x, sa.y); s1 = fpack(sa.z, sa.w);
                s2 = fpack(sb.x, sb.y); s3 = fpack(sb.z, sb.w);
            }
            const int p = i & 3;
            f2 a = fmul2(qv[p][0], s0);
            a = ffma2(qv[p][1], s1, a);
            a = ffma2(qv[p][2], s2, a);
            a = ffma2(qv[p][3], s3, a);
            float x, y; funpack(a, x, y);
            part[i & 7] = x + y;
            if ((i & 7) == 7) {
                float red = rscatter8(part, lane8);
                const int pp = lane8 & 3;
                const int jj = 2 * (i >> 3) + (lane8 >> 2);
                s_e[egbase + pp * EPOS + jj] = red + s_pb[jj];
            }
        }
    }
    __syncwarp();

    // ========== PHASE 1: scores -> e (far-first rows, ring-4 prefetch) ==========
    {
        f2 kbuf[RING][4];
        #pragma unroll
        for (int r = 0; r < RING; r++) {
            int rr = n0 + ROW_T[r];
            int rc = (rr < 0) ? 0 : rr;
            const float4* kr = kb4 + (size_t)rc * HD4;
            float4 a = kr[lane8], b = kr[lane8 + 8];
            kbuf[r][0] = fpack(a.x, a.y); kbuf[r][1] = fpack(a.z, a.w);
            kbuf[r][2] = fpack(b.x, b.y); kbuf[r][3] = fpack(b.z, b.w);
        }

        #pragma unroll
        for (int i = 0; i < NSLOT; i++) {
            const int r  = SLOT_ROW[i];
            const int bi = r % RING;
            const int p  = SLOT_P[i];

            f2 a = fmul2(qv[p][0], kbuf[bi][0]);
            a = ffma2(qv[p][1], kbuf[bi][1], a);
            a = ffma2(qv[p][2], kbuf[bi][2], a);
            a = ffma2(qv[p][3], kbuf[bi][3], a);
            float x, y; funpack(a, x, y);
            part[i & 7] = x + y;

            // last slot of this row -> refill buffer with row r+RING
            if (((i == NSLOT - 1) || (SLOT_ROW[i + 1] != r)) && (r + RING) < NROW) {
                int rr = n0 + ROW_T[r + RING];
                int rc = (rr < 0) ? 0 : rr;
                const float4* kr = kb4 + (size_t)rc * HD4;
                float4 fa = kr[lane8], fb = kr[lane8 + 8];
                kbuf[bi][0] = fpack(fa.x, fa.y); kbuf[bi][1] = fpack(fa.z, fa.w);
                kbuf[bi][2] = fpack(fb.x, fb.y); kbuf[bi][3] = fpack(fb.z, fb.w);
            }

            if ((i & 7) == 7) {
                float red = rscatter8(part, lane8);
                const int base = i - 7;
                const int tt = c_T[base + lane8];
                const int pp = c_P[base + lane8];
                const int jj = c_J[base + lane8];
                const int addr = egbase + pp * EPOS + jj;
                const float validf = (n0 + tt >= 0) ? 1.0f : 0.0f;
                // No max-subtraction: scores are O(+-8), far below exp overflow.
                float e = ex2f(red + s_e[addr]) * validf;
                s_e[addr] = e;
            }
        }
    }
    __syncwarp();

    // ========== denominators ==========
    if (lane8 < 4) {
        const float4* ep = (const float4*)&s_e[egbase + lane8 * EPOS];
        float4 a = ep[0], b = ep[1], c = ep[2], d = ep[3], e4 = ep[4];
        float s = a.x + a.y + a.z + a.w + b.x + b.y + b.z + b.w
                + c.x + c.y + c.z + c.w + d.x + d.y + d.z + d.w
                + e4.x + e4.y + e4.z + e4.w;
        s_e[egbase + lane8 * EPOS + 20] = 1.0f / fmaxf(s, 1e-30f);
    }
    __syncwarp();

    // ========== PHASE 2: out = (sum_j e * v) * inv (same ring streaming) ==========
    {
        f2 oacc[4][4];
        #pragma unroll
        for (int p = 0; p < 4; p++)
            #pragma unroll
            for (int c = 0; c < 4; c++) oacc[p][c] = fpack(0.f, 0.f);

        f2 vbuf[RING][4];
        #pragma unroll
        for (int r = 0; r < RING; r++) {
            int rr = n0 + ROW_T[r];
            int rc = (rr < 0) ? 0 : rr;     // e == 0 when masked, clamp safe
            const float4* vr = vb4 + (size_t)rc * HD4;
            float4 a = vr[lane8], b = vr[lane8 + 8];
            vbuf[r][0] = fpack(a.x, a.y); vbuf[r][1] = fpack(a.z, a.w);
            vbuf[r][2] = fpack(b.x, b.y); vbuf[r][3] = fpack(b.z, b.w);
        }

        #pragma unroll
        for (int i = 0; i < NSLOT; i++) {
            const int r  = SLOT_ROW[i];
            const int bi = r % RING;
            const int p  = SLOT_P[i];

            const float e = s_e[egbase + p * EPOS + SLOT_J[i]];
            f2 e2 = fpack(e, e);
            oacc[p][0] = ffma2(e2, vbuf[bi][0], oacc[p][0]);
            oacc[p][1] = ffma2(e2, vbuf[bi][1], oacc[p][1]);
            oacc[p][2] = ffma2(e2, vbuf[bi][2], oacc[p][2]);
            oacc[p][3] = ffma2(e2, vbuf[bi][3], oacc[p][3]);

            if (((i == NSLOT - 1) || (SLOT_ROW[i + 1] != r)) && (r + RING) < NROW) {
                int rr = n0 + ROW_T[r + RING];
                int rc = (rr < 0) ? 0 : rr;
                const float4* vr = vb4 + (size_t)rc * HD4;
                float4 fa = vr[lane8], fb = vr[lane8 + 8];
                vbuf[bi][0] = fpack(fa.x, fa.y); vbuf[bi][1] = fpack(fa.z, fa.w);
                vbuf[bi][2] = fpack(fb.x, fb.y); vbuf[bi][3] = fpack(fb.z, fb.w);
            }
        }

        #pragma unroll
        for (int p = 0; p < 4; p++) {
            const float inv = s_e[egbase + p * EPOS + 20];
            f2 iv = fpack(inv, inv);
            f2 r0 = fmul2(oacc[p][0], iv);
            f2 r1 = fmul2(oacc[p][1], iv);
            f2 r2 = fmul2(oacc[p][2], iv);
            f2 r3 = fmul2(oacc[p][3], iv);
            float4 oA, oB;
            funpack(r0, oA.x, oA.y); funpack(r1, oA.z, oA.w);
            funpack(r2, oB.x, oB.y); funpack(r3, oB.z, oB.w);
            float4* o4 = (float4*)out + bh_row0 + (size_t)(n0 + p) * HD4;
            o4[lane8]     = oA;
            o4[lane8 + 8] = oB;
        }
    }
}

extern "C" void kernel_launch(void* const* d_in, const int* in_sizes, int n_in,
                              void* d_out, int out_size)
{
    const float* q  = (const float*)d_in[0];
    const float* k  = (const float*)d_in[1];
    const float* v  = (const float*)d_in[2];
    const float* pb = (const float*)d_in[3];
    const float* se = (const float*)d_in[4];
    float* out = (float*)d_out;

    const int blocks = NB * NH * (NSEQ / POS_PER_CTA);   // 8192
    dsqg_attn_kernel<<<blocks, 256>>>(q, k, v, pb, se, out);
}